// round 8
// baseline (speedup 1.0000x reference)
#include <cuda_runtime.h>
#include <float.h>

// Density_loss via sorted-axis kNN:
//   per (cloud,batch): bitonic-sort points by x in SMEM; each warp owns 32
//   consecutive sorted queries; expand outward left/right with (dx)^2 pruning.
//   Mean of 16 smallest squared distances per point -> per-cloud mean -> MSE.

#define NPTS  2048
#define BLK   256
#define TILES (NPTS / BLK)   // 8
#define BATCH 8
#define KNN   16
#define FULLM 0xffffffffu

__device__ float g_partials[2 * BATCH * TILES];

__global__ __launch_bounds__(BLK, 1)
void knn_sorted_kernel(const float* __restrict__ seed,
                       const float* __restrict__ gt) {
    __shared__ float4         sp[NPTS];    // 32 KB: {-2x,-2y,-2z,|p|^2}, x-sorted
    __shared__ float          skey[NPTS];  //  8 KB: sorted x values (prune keys)
    __shared__ unsigned short sidx[NPTS];  //  4 KB: sort payload (orig index)
    __shared__ float          sred[BLK / 32];

    const int tile  = blockIdx.x;
    const int b     = blockIdx.y;
    const int which = blockIdx.z;
    const float* __restrict__ pts =
        (which == 0 ? seed : gt) + (size_t)b * NPTS * 3;

    // ---- Stage sort keys (x coordinate) + identity payload ----
    for (int i = threadIdx.x; i < NPTS; i += BLK) {
        skey[i] = pts[3 * i];
        sidx[i] = (unsigned short)i;
    }
    __syncthreads();

    // ---- Bitonic sort ascending by key (2048 elems, 1024 CE/substep) ----
    for (int k = 2; k <= NPTS; k <<= 1) {
        for (int j = k >> 1; j > 0; j >>= 1) {
            for (int t = threadIdx.x; t < NPTS / 2; t += BLK) {
                const int i = ((t & ~(j - 1)) << 1) | (t & (j - 1));
                const int p = i | j;
                const bool up = ((i & k) == 0);
                const float a = skey[i], c = skey[p];
                if ((a > c) == up) {
                    skey[i] = c; skey[p] = a;
                    const unsigned short ta = sidx[i];
                    sidx[i] = sidx[p]; sidx[p] = ta;
                }
            }
            __syncthreads();
        }
    }

    // ---- Gather transformed points in sorted order ----
    for (int i = threadIdx.x; i < NPTS; i += BLK) {
        const int id = sidx[i];
        const float x = __ldg(pts + 3 * id + 0);
        const float y = __ldg(pts + 3 * id + 1);
        const float z = __ldg(pts + 3 * id + 2);
        sp[i] = make_float4(-2.0f * x, -2.0f * y, -2.0f * z,
                            fmaf(x, x, fmaf(y, y, z * z)));
    }
    __syncthreads();

    // ---- kNN: each warp owns 32 consecutive sorted queries ----
    const int lane = threadIdx.x & 31;
    const int w0   = tile * BLK + (threadIdx.x >> 5) * 32;
    const float4 q = sp[w0 + lane];
    const float Qx = -0.5f * q.x;   // actual x of this query
    const float Qy = -0.5f * q.y;
    const float Qz = -0.5f * q.z;
    const float Qs = q.w;

    float best[KNN];
#pragma unroll
    for (int k = 0; k < KNN; ++k) best[k] = FLT_MAX;
    float thresh = FLT_MAX;

    auto insert = [&](float d) {
        if (__any_sync(FULLM, d < thresh)) {
            float v = (d < thresh) ? d : FLT_MAX;  // non-improving falls off end
#pragma unroll
            for (int k = 0; k < KNN; ++k) {
                const float lo = fminf(best[k], v);
                v       = fmaxf(best[k], v);
                best[k] = lo;
            }
            thresh = best[KNN - 1];
        }
    };

    // Phase 1: the warp's own 32 candidates (includes self, d ~ 0).
#pragma unroll 4
    for (int j = w0; j < w0 + 32; ++j) {
        const float4 p = sp[j];
        insert(fmaf(p.x, Qx, fmaf(p.y, Qy, fmaf(p.z, Qz, Qs + p.w))));
    }

    // Phase 2: expand outward, chunk=4 per step, prune on (dx)^2 >= thresh.
    int l = w0 - 1;
    int r = w0 + 32;
    const float xLo = __shfl_sync(FULLM, Qx, 0);   // leftmost query x in warp
    const float xHi = __shfl_sync(FULLM, Qx, 31);  // rightmost query x
    bool haveL = (l >= 0);
    bool haveR = (r < NPTS);

    while (haveL | haveR) {
        const bool goLeft =
            haveL && (!haveR || (xLo - skey[l]) <= (skey[r] - xHi));
        if (goLeft) {
            int jend = l - 4;            // exclusive lower bound
            if (jend < -1) jend = -1;
            float far_dx = 0.0f;
            for (int j = l; j > jend; --j) {
                const float4 p = sp[j];
                const float d =
                    fmaf(p.x, Qx, fmaf(p.y, Qy, fmaf(p.z, Qz, Qs + p.w)));
                insert(d);
                far_dx = fmaf(0.5f, p.x, Qx);    // Qx - x_j
            }
            l = jend;
            const bool pruned =
                __all_sync(FULLM, far_dx * far_dx >= thresh);
            haveL = (l >= 0) && !pruned;
        } else {
            int jend = r + 4;            // exclusive upper bound
            if (jend > NPTS) jend = NPTS;
            float far_dx = 0.0f;
            for (int j = r; j < jend; ++j) {
                const float4 p = sp[j];
                const float d =
                    fmaf(p.x, Qx, fmaf(p.y, Qy, fmaf(p.z, Qz, Qs + p.w)));
                insert(d);
                far_dx = fmaf(0.5f, p.x, Qx);    // Qx - x_j (sign irrelevant)
            }
            r = jend;
            const bool pruned =
                __all_sync(FULLM, far_dx * far_dx >= thresh);
            haveR = (r < NPTS) && !pruned;
        }
    }

    // ---- Per-point mean of 16 NN, then deterministic block reduction ----
    float s = 0.0f;
#pragma unroll
    for (int k = 0; k < KNN; ++k) s += best[k];
    s *= (1.0f / KNN);

#pragma unroll
    for (int off = 16; off > 0; off >>= 1)
        s += __shfl_down_sync(FULLM, s, off);
    if (lane == 0) sred[threadIdx.x >> 5] = s;
    __syncthreads();
    if (threadIdx.x == 0) {
        float t = 0.0f;
#pragma unroll
        for (int w = 0; w < BLK / 32; ++w) t += sred[w];
        g_partials[(which * BATCH + b) * TILES + tile] = t;
    }
}

__global__ void finalize_kernel(float* __restrict__ out) {
    const int lane = threadIdx.x;   // 32 threads
    float s = 0.0f;
    if (lane < 2 * BATCH) {
        const int base = lane * TILES;     // lane = which*8 + b
#pragma unroll
        for (int t = 0; t < TILES; ++t) s += g_partials[base + t];
        s *= (1.0f / NPTS);
    }
    const float other = __shfl_xor_sync(FULLM, s, 8);  // pair seed<->gt
    const float diff = s - other;
    float d2 = diff * diff;
    if (lane >= 8) d2 = 0.0f;
#pragma unroll
    for (int off = 4; off > 0; off >>= 1)
        d2 += __shfl_down_sync(FULLM, d2, off);
    if (lane == 0) out[0] = d2 * (1.0f / BATCH);
}

extern "C" void kernel_launch(void* const* d_in, const int* in_sizes, int n_in,
                              void* d_out, int out_size) {
    const float* seed = (const float*)d_in[0];
    const float* gt_s = (const float*)d_in[1];
    float* out = (float*)d_out;

    dim3 grid(TILES, BATCH, 2);
    knn_sorted_kernel<<<grid, BLK>>>(seed, gt_s);
    finalize_kernel<<<1, 32>>>(out);
}

// round 9
// speedup vs baseline: 1.8460x; 1.8460x over previous
#include <cuda_runtime.h>
#include <float.h>

// Density_loss via once-per-cloud x-sort + regular symmetric-window kNN scan.
// B=8, N=2048, C=3, K=16.  d(q,p) = |q|^2+|p|^2-2q.p (expansion form, fp32).

#define NPTS   2048
#define BLK    256
#define TILES  (NPTS / BLK)   // 8
#define BATCH  8
#define CLOUDS (2 * BATCH)    // 16
#define KNN    16
#define WINA   128            // phase-A half-window (regular)
#define CHUNK  16             // phase-B chunk per prune vote
#define FULLM  0xffffffffu

// Sorted, transformed points per cloud: {-2x, -2y, -2z, |p|^2}, ascending x.
__device__ float4 g_sorted[CLOUDS * NPTS];     // 512 KB (L2-resident)
__device__ float  g_partials[CLOUDS * TILES];

// ---------------------------------------------------------------------------
// Kernel 1: per-cloud bitonic sort by x (16 CTAs, shared-memory sort).
// ---------------------------------------------------------------------------
__global__ __launch_bounds__(512, 1)
void sort_kernel(const float* __restrict__ seed,
                 const float* __restrict__ gt) {
    __shared__ float          key[NPTS];   // x values
    __shared__ unsigned short idx[NPTS];   // original index payload

    const int cloud = blockIdx.x;          // which*8 + b
    const float* __restrict__ pts =
        ((cloud >> 3) == 0 ? seed : gt) + (size_t)(cloud & 7) * NPTS * 3;

    for (int i = threadIdx.x; i < NPTS; i += 512) {
        key[i] = pts[3 * i];
        idx[i] = (unsigned short)i;
    }
    __syncthreads();

    for (int k = 2; k <= NPTS; k <<= 1) {
        for (int j = k >> 1; j > 0; j >>= 1) {
            for (int t = threadIdx.x; t < NPTS / 2; t += 512) {
                const int i = ((t & ~(j - 1)) << 1) | (t & (j - 1));
                const int p = i | j;
                const bool up = ((i & k) == 0);
                const float a = key[i], c = key[p];
                if ((a > c) == up) {
                    key[i] = c; key[p] = a;
                    const unsigned short ta = idx[i];
                    idx[i] = idx[p]; idx[p] = ta;
                }
            }
            __syncthreads();
        }
    }

    // Gather in sorted order, transform, write out.
    for (int i = threadIdx.x; i < NPTS; i += 512) {
        const int id = idx[i];
        const float x = pts[3 * id + 0];
        const float y = pts[3 * id + 1];
        const float z = pts[3 * id + 2];
        g_sorted[cloud * NPTS + i] =
            make_float4(-2.0f * x, -2.0f * y, -2.0f * z,
                        fmaf(x, x, fmaf(y, y, z * z)));
    }
}

// ---------------------------------------------------------------------------
// Kernel 2: kNN over sorted order — regular symmetric window + chunked prune.
// ---------------------------------------------------------------------------
__global__ __launch_bounds__(BLK, 1)
void knn_kernel() {
    __shared__ float4 sp[NPTS];            // 32 KB sorted transformed points
    __shared__ float  sred[BLK / 32];

    const int tile  = blockIdx.x;
    const int b     = blockIdx.y;
    const int which = blockIdx.z;
    const int cloud = which * BATCH + b;

    const float4* __restrict__ src = g_sorted + cloud * NPTS;
    for (int i = threadIdx.x; i < NPTS; i += BLK) sp[i] = src[i];
    __syncthreads();

    const int lane  = threadIdx.x & 31;
    const int qrank = tile * BLK + threadIdx.x;   // this thread's sorted rank
    const float4 q  = sp[qrank];
    const float Qx  = -0.5f * q.x;                // actual x of query
    const float Qy  = q.y;                        // keep packed form coeffs
    const float Qz  = q.z;
    const float Qs  = q.w;
    // dist(p) = p.x*(-0.5*q.x is NOT the form) — use symmetric expansion:
    // d = q.w + p.w + 0.5*(q.x*p.x + q.y*p.y + q.z*p.z)  since q.x=-2x etc:
    //   q.x*p.x = 4 xq xp -> 0.5* gives 2 xq xp; we need -2 xq xp. So use -0.5.
    const float cx = -0.5f * q.x;   // = xq
    const float cy = -0.5f * q.y;   // = yq
    const float cz = -0.5f * q.z;   // = zq

    float best[KNN];
#pragma unroll
    for (int k = 0; k < KNN; ++k) best[k] = FLT_MAX;
    float thresh = FLT_MAX;

    auto dist = [&](const float4 p) -> float {
        // p holds {-2x,-2y,-2z,|p|^2}: d = fma(-2px, xq, ...) + (|q|^2+|p|^2)
        return fmaf(p.x, cx, fmaf(p.y, cy, fmaf(p.z, cz, Qs + p.w)));
    };
    auto insert = [&](float d) {
        if (__any_sync(FULLM, d < thresh)) {
            float v = (d < thresh) ? d : FLT_MAX;
#pragma unroll
            for (int k = 0; k < KNN; ++k) {
                const float lo = fminf(best[k], v);
                v       = fmaxf(best[k], v);
                best[k] = lo;
            }
            thresh = best[KNN - 1];
        }
    };

    // ---- Phase A: regular symmetric window, ranks [q-WINA, q+WINA-1] ----
#pragma unroll 4
    for (int off = 0; off < WINA; ++off) {
        const int jr = qrank + off;            // off=0 -> self (d ~ 0)
        const int jl = qrank - 1 - off;
        const int jrc = (jr < NPTS) ? jr : NPTS - 1;
        const int jlc = (jl >= 0) ? jl : 0;
        float dr = dist(sp[jrc]);
        float dl = dist(sp[jlc]);
        dr = (jr < NPTS) ? dr : FLT_MAX;
        dl = (jl >= 0)   ? dl : FLT_MAX;
        insert(dr);
        insert(dl);
    }

    // ---- Phase B: extend left in chunks with frontier prune vote ----
    {
        int jl = qrank - 1 - WINA;             // nearest unscanned left rank
        while (true) {
            const int jc = (jl >= 0) ? jl : 0;
            const float xn = -0.5f * sp[jc].x;
            const float dx = Qx - xn;          // >= 0 by sortedness
            const bool pruned = (jl < 0) || (dx * dx >= thresh);
            if (__all_sync(FULLM, pruned)) break;
#pragma unroll
            for (int u = 0; u < CHUNK; ++u) {
                const int j  = jl - u;
                const int jcc = (j >= 0) ? j : 0;
                float d = dist(sp[jcc]);
                d = (j >= 0) ? d : FLT_MAX;
                insert(d);
            }
            jl -= CHUNK;
        }
    }

    // ---- Phase C: extend right in chunks with frontier prune vote ----
    {
        int jr = qrank + WINA;                 // nearest unscanned right rank
        while (true) {
            const int jc = (jr < NPTS) ? jr : NPTS - 1;
            const float xn = -0.5f * sp[jc].x;
            const float dx = xn - Qx;          // >= 0 by sortedness
            const bool pruned = (jr >= NPTS) || (dx * dx >= thresh);
            if (__all_sync(FULLM, pruned)) break;
#pragma unroll
            for (int u = 0; u < CHUNK; ++u) {
                const int j  = jr + u;
                const int jcc = (j < NPTS) ? j : NPTS - 1;
                float d = dist(sp[jcc]);
                d = (j < NPTS) ? d : FLT_MAX;
                insert(d);
            }
            jr += CHUNK;
        }
    }

    // ---- Mean of 16 NN per point, deterministic block reduction ----
    float s = 0.0f;
#pragma unroll
    for (int k = 0; k < KNN; ++k) s += best[k];
    s *= (1.0f / KNN);

#pragma unroll
    for (int off = 16; off > 0; off >>= 1)
        s += __shfl_down_sync(FULLM, s, off);
    if (lane == 0) sred[threadIdx.x >> 5] = s;
    __syncthreads();
    if (threadIdx.x == 0) {
        float t = 0.0f;
#pragma unroll
        for (int w = 0; w < BLK / 32; ++w) t += sred[w];
        g_partials[cloud * TILES + tile] = t;
    }
}

// ---------------------------------------------------------------------------
// Kernel 3: finalize MSE.
// ---------------------------------------------------------------------------
__global__ void finalize_kernel(float* __restrict__ out) {
    const int lane = threadIdx.x;   // 32 threads
    float s = 0.0f;
    if (lane < CLOUDS) {
        const int base = lane * TILES;       // lane = which*8 + b
#pragma unroll
        for (int t = 0; t < TILES; ++t) s += g_partials[base + t];
        s *= (1.0f / NPTS);
    }
    const float other = __shfl_xor_sync(FULLM, s, 8);   // pair seed<->gt
    const float diff = s - other;
    float d2 = diff * diff;
    if (lane >= 8) d2 = 0.0f;
#pragma unroll
    for (int off = 4; off > 0; off >>= 1)
        d2 += __shfl_down_sync(FULLM, d2, off);
    if (lane == 0) out[0] = d2 * (1.0f / BATCH);
}

extern "C" void kernel_launch(void* const* d_in, const int* in_sizes, int n_in,
                              void* d_out, int out_size) {
    const float* seed = (const float*)d_in[0];
    const float* gt_s = (const float*)d_in[1];
    float* out = (float*)d_out;

    sort_kernel<<<CLOUDS, 512>>>(seed, gt_s);
    dim3 grid(TILES, BATCH, 2);
    knn_kernel<<<grid, BLK>>>();
    finalize_kernel<<<1, 32>>>(out);
}